// round 15
// baseline (speedup 1.0000x reference)
#include <cuda_runtime.h>
#include <cuda_fp16.h>
#include <cstdint>

// ---------------------------------------------------------------------------
// Problem constants
// ---------------------------------------------------------------------------
constexpr int BB   = 128;
constexpr int CC   = 64;
constexpr int K1   = 192;    // 3*C perception channels
constexpr int M1   = 512;    // MLP dim
constexpr int HH   = 40;
constexpr int WW   = 40;
constexpr int PX   = 1600;   // H*W
constexpr int PXP  = 1664;   // padded to 26*64
constexpr float LN_EPS = 1e-5f;

// ---------------------------------------------------------------------------
// Device scratch
// ---------------------------------------------------------------------------
__device__ __half  g_perc[(size_t)BB * PXP * K1];   // 81 MB fp16
__device__ __half  g_y[(size_t)BB * PXP * M1];      // 218 MB fp16 (compacted rows)
__device__ __half  g_w1h[M1 * K1];                  // [512][192] fp16
__device__ __half  g_w2h[CC * M1];                  // [64][512] fp16
__device__ __half2 g_lnwb[(size_t)PX * M1];         // [p][m] packed (w, b) fp16
__device__ float   g_part[BB * 52 * 2];
__device__ float   g_stats[BB * 2];
__device__ int     g_plist[PX];                     // compacted px list
__device__ int     g_cidx[PX];                      // px -> compact idx or -1
__device__ int     g_cnt;

// ---------------------------------------------------------------------------
// Helpers (base-ISA only: ldmatrix / mma.sync / cp.async)
// ---------------------------------------------------------------------------
__device__ __forceinline__ uint32_t smem_u32(const void* p) {
    uint32_t a;
    asm("{ .reg .u64 t; cvta.to.shared.u64 t, %1; cvt.u32.u64 %0, t; }"
        : "=r"(a) : "l"(p));
    return a;
}
#define SW128(o) ((o) ^ (((o) >> 3) & 0x70))

__device__ __forceinline__ void sts128(uint32_t a, uint4 v) {
    asm volatile("st.shared.v4.b32 [%0], {%1,%2,%3,%4};"
                 :: "r"(a), "r"(v.x), "r"(v.y), "r"(v.z), "r"(v.w) : "memory");
}
__device__ __forceinline__ void cp16(uint32_t dst, const void* src) {
    asm volatile("cp.async.cg.shared.global [%0], [%1], 16;"
                 :: "r"(dst), "l"(src) : "memory");
}
#define CP_COMMIT() asm volatile("cp.async.commit_group;" ::: "memory")
#define CP_WAIT(n)  asm volatile("cp.async.wait_group %0;" :: "n"(n) : "memory")

__device__ __forceinline__ void ldm_x4(uint32_t addr, uint32_t& r0, uint32_t& r1,
                                       uint32_t& r2, uint32_t& r3) {
    asm volatile("ldmatrix.sync.aligned.m8n8.x4.shared.b16 {%0,%1,%2,%3}, [%4];"
                 : "=r"(r0), "=r"(r1), "=r"(r2), "=r"(r3) : "r"(addr));
}
__device__ __forceinline__ void mma_f16(float* c, const uint32_t* a,
                                        uint32_t b0, uint32_t b1) {
    asm volatile(
        "mma.sync.aligned.m16n8k16.row.col.f32.f16.f16.f32 "
        "{%0,%1,%2,%3},{%4,%5,%6,%7},{%8,%9},{%0,%1,%2,%3};"
        : "+f"(c[0]), "+f"(c[1]), "+f"(c[2]), "+f"(c[3])
        : "r"(a[0]), "r"(a[1]), "r"(a[2]), "r"(a[3]), "r"(b0), "r"(b1));
}

__device__ __forceinline__ uint32_t pack2h(__half a, __half b) {
    return (uint32_t)__half_as_ushort(a) | ((uint32_t)__half_as_ushort(b) << 16);
}

// ---------------------------------------------------------------------------
// Kernel 1 (fused pre): perc | w-casts | perc-pad | compact | lnwb transpose
// ---------------------------------------------------------------------------
constexpr int NB_PERC = HH * BB;               // 5120
constexpr int WPREP_TOTAL = M1 * K1 + CC * M1; // 131072
constexpr int NB_W    = (WPREP_TOTAL + 319) / 320;   // 410
constexpr int NB_PAD  = BB;                    // 128
constexpr int NB_LNT  = (M1 / 32) * (PX / 32); // 800
constexpr int NB_PRE  = NB_PERC + NB_W + NB_PAD + 1 + NB_LNT;

__global__ __launch_bounds__(320) void pre_kernel(
    const float* __restrict__ state, const float* __restrict__ w1,
    const float* __restrict__ w2, const float* __restrict__ lnw,
    const float* __restrict__ lnb, const int* __restrict__ mask,
    float* __restrict__ out) {
    __shared__ __align__(16) char fsm[15488];
    int bx = blockIdx.x;
    int tid = threadIdx.x;

    if (bx < NB_PERC) {
        // ---- perception (fp16 out) + out=state passthrough ----
        __half (*sp)[K1] = reinterpret_cast<__half(*)[K1]>(fsm);
        int h = bx % HH;
        int b = bx / HH;
        int c   = tid / 5;
        int seg = tid % 5;
        int w0  = seg * 8;
        const float* s = state + ((size_t)b * CC + c) * PX;
        float v[3][10];
#pragma unroll
        for (int r = 0; r < 3; r++) {
            int hh = h + r - 1;
            if (hh >= 0 && hh < HH) {
                const float* rp = s + hh * WW;
                float4 a = *reinterpret_cast<const float4*>(rp + w0);
                float4 d = *reinterpret_cast<const float4*>(rp + w0 + 4);
                v[r][0] = (w0 > 0) ? rp[w0 - 1] : 0.f;
                v[r][1] = a.x; v[r][2] = a.y; v[r][3] = a.z; v[r][4] = a.w;
                v[r][5] = d.x; v[r][6] = d.y; v[r][7] = d.z; v[r][8] = d.w;
                v[r][9] = (w0 + 8 < WW) ? rp[w0 + 8] : 0.f;
            } else {
#pragma unroll
                for (int q = 0; q < 10; q++) v[r][q] = 0.f;
            }
        }
#pragma unroll
        for (int i = 0; i < 8; i++) {
            float sx = -v[0][i] + v[0][i + 2] - 2.f * v[1][i] + 2.f * v[1][i + 2]
                       - v[2][i] + v[2][i + 2];
            float sy = -v[0][i] - 2.f * v[0][i + 1] - v[0][i + 2]
                       + v[2][i] + 2.f * v[2][i + 1] + v[2][i + 2];
            int w = w0 + i;
            sp[w][3 * c + 0] = __float2half_rn(sx);
            sp[w][3 * c + 1] = __float2half_rn(sy);
            sp[w][3 * c + 2] = __float2half_rn(v[1][i + 1]);
        }
        float* op = out + ((size_t)b * CC + c) * PX + h * WW + w0;
        *reinterpret_cast<float4*>(op)     = make_float4(v[1][1], v[1][2], v[1][3], v[1][4]);
        *reinterpret_cast<float4*>(op + 4) = make_float4(v[1][5], v[1][6], v[1][7], v[1][8]);
        __syncthreads();
        const uint4* src = reinterpret_cast<const uint4*>(&sp[0][0]);
        uint4* dst = reinterpret_cast<uint4*>(g_perc + ((size_t)b * PXP + h * WW) * K1);
#pragma unroll
        for (int i = 0; i < 3; i++) dst[tid + i * 320] = src[tid + i * 320];
    } else if (bx < NB_PERC + NB_W) {
        // ---- weight casts ----
        int idx = (bx - NB_PERC) * 320 + tid;
        if (idx < M1 * K1) {
            g_w1h[idx] = __float2half_rn(w1[idx]);
        } else if (idx < WPREP_TOTAL) {
            int j = idx - M1 * K1;
            g_w2h[j] = __float2half_rn(w2[j]);
        }
    } else if (bx < NB_PERC + NB_W + NB_PAD) {
        // ---- perc pad rows (px 1600..1663): 1536 uint4 per b ----
        int b = bx - NB_PERC - NB_W;
        uint4 z = make_uint4(0, 0, 0, 0);
        uint4* dst = reinterpret_cast<uint4*>(g_perc + ((size_t)b * PXP + PX) * K1);
#pragma unroll
        for (int i = 0; i < 5; i++) {
            int j = tid + i * 320;
            if (j < 1536) dst[j] = z;
        }
    } else if (bx == NB_PERC + NB_W + NB_PAD) {
        // ---- mask compaction (deterministic) ----
        int* sm = reinterpret_cast<int*>(fsm);
        for (int i = tid; i < PX; i += 320) sm[i] = mask[i];
        __syncthreads();
        if (tid == 0) {
            int c = 0;
            for (int p = 0; p < PX; p++) {
                if (sm[p] != 0) { g_plist[c] = p; g_cidx[p] = c; c++; }
                else            { g_cidx[p] = -1; }
            }
            g_cnt = c;
        }
    } else {
        // ---- lnw+lnb 32x32 tiled transpose -> packed half2 (w, b) ----
        float (*tw)[33] = reinterpret_cast<float(*)[33]>(fsm);
        float (*tb)[33] = reinterpret_cast<float(*)[33]>(fsm + 4224);
        int t = bx - (NB_PERC + NB_W + NB_PAD + 1);
        int pm = t / 50;           // m tile
        int pp = t % 50;           // p tile
        if (tid < 256) {
            int r8 = tid >> 5, cc = tid & 31;
#pragma unroll
            for (int q = 0; q < 4; q++) {
                int r = q * 8 + r8;
                size_t off = (size_t)(pm * 32 + r) * PX + pp * 32 + cc;
                tw[r][cc] = lnw[off];
                tb[r][cc] = lnb[off];
            }
        }
        __syncthreads();
        if (tid < 256) {
            int r8 = tid >> 5, cc = tid & 31;
#pragma unroll
            for (int q = 0; q < 4; q++) {
                int r = q * 8 + r8;
                size_t e = (size_t)(pp * 32 + r) * M1 + pm * 32 + cc;
                g_lnwb[e] = __floats2half2_rn(tw[cc][r], tb[cc][r]);
            }
        }
    }
}

// ---------------------------------------------------------------------------
// Kernel 2: GEMM1 (mma.sync fp16) CTA tile 64px x 256mlp, warp tile 32x64.
//   Full-A preload (3 x 8KB) + double-buffered B (2 x 32KB) = 88KB smem.
//   launch_bounds(256,2) -> 2 CTAs/SM. Shuffle stats + coalesced y stores.
// ---------------------------------------------------------------------------
constexpr int G1_BOFF  = 24576;   // B buffers start after 3 A sub-tiles
constexpr int YT_PITCH = 264;     // fp16 stage tile pitch (conflict-free)

__global__ __launch_bounds__(256, 2) void gemm1_kernel() {
    extern __shared__ char dsm[];
    __shared__ float wred[16];
    uint32_t base = smem_u32(dsm);
    int tid = threadIdx.x;
    int lane = tid & 31, wid = tid >> 5;
    int nt = blockIdx.x;   // 0..1  (mlp half, 256 each)
    int pt = blockIdx.y;   // 0..25 (px tile of 64)
    int b  = blockIdx.z;

    const __half* Ab = g_perc + ((size_t)b * PXP + pt * 64) * K1;
    const __half* Bb = g_w1h + (size_t)(nt * 256) * K1;

    int m0 = (wid & 1) * 32;
    int n0 = (wid >> 1) * 64;
    int a_row  = m0 + (lane & 15);
    int a_byte = (lane >> 4) << 4;
    int qq     = lane >> 3;
    int b_row  = n0 + ((qq >> 1) << 3) + (lane & 7);
    int b_byte = (qq & 1) << 4;

    float acc[2][8][4] = {};

    // prologue: ALL of A (3 sub-tiles) + B chunk 0 -> group 0; B chunk 1 -> group 1
    {
#pragma unroll
        for (int ko = 0; ko < 3; ko++) {
            uint32_t sA = base + ko * 8192;
#pragma unroll
            for (int i = 0; i < 2; i++) {
                int g = tid + i * 256, r = g >> 3, c = g & 7;
                cp16(sA + SW128(r * 128 + c * 16), Ab + (size_t)r * K1 + ko * 64 + c * 8);
            }
        }
        uint32_t sB = base + G1_BOFF;
#pragma unroll
        for (int i = 0; i < 8; i++) {
            int g = tid + i * 256, r = g >> 3, c = g & 7;
            cp16(sB + SW128(r * 128 + c * 16), Bb + (size_t)r * K1 + c * 8);
        }
        CP_COMMIT();
        uint32_t sB1 = base + G1_BOFF + 32768;
#pragma unroll
        for (int i = 0; i < 8; i++) {
            int g = tid + i * 256, r = g >> 3, c = g & 7;
            cp16(sB1 + SW128(r * 128 + c * 16), Bb + (size_t)r * K1 + 64 + c * 8);
        }
        CP_COMMIT();
    }

#pragma unroll 1
    for (int ch = 0; ch < 3; ch++) {
        if (ch < 2) { CP_WAIT(1); } else { CP_WAIT(0); }
        __syncthreads();
        uint32_t sA = base + ch * 8192;
        uint32_t sB = base + G1_BOFF + (ch & 1) * 32768;
#pragma unroll
        for (int kk = 0; kk < 4; kk++) {
            int kb = kk * 32;
            uint32_t a[2][4];
#pragma unroll
            for (int mi = 0; mi < 2; mi++)
                ldm_x4(sA + SW128((a_row + mi * 16) * 128 + kb + a_byte),
                       a[mi][0], a[mi][1], a[mi][2], a[mi][3]);
            uint32_t bf[4][4];
#pragma unroll
            for (int n2 = 0; n2 < 4; n2++)
                ldm_x4(sB + SW128((b_row + n2 * 16) * 128 + kb + b_byte),
                       bf[n2][0], bf[n2][1], bf[n2][2], bf[n2][3]);
#pragma unroll
            for (int mi = 0; mi < 2; mi++)
#pragma unroll
                for (int ni = 0; ni < 8; ni++)
                    mma_f16(acc[mi][ni], a[mi],
                            bf[ni >> 1][(ni & 1) * 2], bf[ni >> 1][(ni & 1) * 2 + 1]);
        }
        if (ch == 0) {
            // prefetch B chunk 2 into buffer 0 (just finished reading it)
            __syncthreads();
            uint32_t sB2 = base + G1_BOFF;
#pragma unroll
            for (int i = 0; i < 8; i++) {
                int g = tid + i * 256, r = g >> 3, c = g & 7;
                cp16(sB2 + SW128(r * 128 + c * 16), Bb + (size_t)r * K1 + 128 + c * 8);
            }
            CP_COMMIT();
        }
    }
    __syncthreads();

    // ---- epilogue ----
    float s = 0.f, s2 = 0.f;
#pragma unroll
    for (int mi = 0; mi < 2; mi++)
#pragma unroll
        for (int ni = 0; ni < 8; ni++) {
            float* c = acc[mi][ni];
            s  += c[0] + c[1] + c[2] + c[3];
            s2 += c[0] * c[0] + c[1] * c[1] + c[2] * c[2] + c[3] * c[3];
        }
#pragma unroll
    for (int o = 16; o > 0; o >>= 1) {
        s  += __shfl_xor_sync(0xffffffffu, s, o);
        s2 += __shfl_xor_sync(0xffffffffu, s2, o);
    }
    if (lane == 0) { wred[wid] = s; wred[8 + wid] = s2; }

    // stage y fp16 into conflict-free tile [64][YT_PITCH]
    __half* yt = reinterpret_cast<__half*>(dsm);
    int cb = n0 + (lane & 3) * 2;
#pragma unroll
    for (int mi = 0; mi < 2; mi++)
#pragma unroll
        for (int half = 0; half < 2; half++) {
            int r = m0 + mi * 16 + (lane >> 2) + half * 8;
            __half* rowp = yt + r * YT_PITCH + cb;
#pragma unroll
            for (int ni = 0; ni < 8; ni++)
                *reinterpret_cast<__half2*>(rowp + ni * 8) =
                    __floats2half2_rn(acc[mi][ni][half * 2], acc[mi][ni][half * 2 + 1]);
        }
    __syncthreads();

    if (tid == 0) {
        float a = 0.f;
#pragma unroll
        for (int i = 0; i < 8; i++) a += wred[i];
        g_part[((b * 26 + pt) * 2 + nt) * 2 + 0] = a;
    } else if (tid == 1) {
        float a = 0.f;
#pragma unroll
        for (int i = 0; i < 8; i++) a += wred[8 + i];
        g_part[((b * 26 + pt) * 2 + nt) * 2 + 1] = a;
    }

    // coalesced masked y copy: one warp per row, 512B uint4 sweep
#pragma unroll
    for (int pass = 0; pass < 8; pass++) {
        int r  = wid + pass * 8;
        int px = pt * 64 + r;
        int ci = (px < PX) ? g_cidx[px] : -1;
        if (ci >= 0) {
            uint4 v = *reinterpret_cast<const uint4*>(yt + r * YT_PITCH + lane * 8);
            *reinterpret_cast<uint4*>(g_y + ((size_t)b * PXP + ci) * M1
                                      + nt * 256 + lane * 8) = v;
        }
    }
}

// ---------------------------------------------------------------------------
// Kernel 3: per-sample LN stats (deterministic fixed order)
// ---------------------------------------------------------------------------
__global__ void stats_kernel() {
    int b = threadIdx.x;
    if (b >= BB) return;
    float s = 0.f, s2 = 0.f;
    for (int i = 0; i < 52; i++) {
        s  += g_part[(b * 52 + i) * 2 + 0];
        s2 += g_part[(b * 52 + i) * 2 + 1];
    }
    float inv = 1.f / (float)(M1 * PX);
    float mu  = s * inv;
    float var = s2 * inv - mu * mu;
    g_stats[b * 2 + 0] = mu;
    g_stats[b * 2 + 1] = rsqrtf(var + LN_EPS);
}

// ---------------------------------------------------------------------------
// Kernel 4: GEMM2 over COMPACTED pixels — PIPELINED, 3 CTAs/SM. (slot 4)
//   smem: sA 16KB | sB 2x8KB | ybuf 16KB = 48KB.
// ---------------------------------------------------------------------------
__global__ __launch_bounds__(256, 3) void gemm2_kernel(
    const float* __restrict__ state, float* __restrict__ out) {
    extern __shared__ char dsm[];
    __shared__ float scl[128];
    __shared__ int   spx[128];
    uint32_t sA  = smem_u32(dsm);
    uint32_t sBb = sA + 16384;
    uint32_t yb  = sA + 32768;
    char* ybg = dsm + 32768;

    int cnt = g_cnt;
    int ct = blockIdx.x;
    if (ct * 128 >= cnt) return;
    int b  = blockIdx.y;

    int tid = threadIdx.x, lane = tid & 31, wid = tid >> 5;
    float mu   = g_stats[b * 2 + 0];
    float rstd = g_stats[b * 2 + 1];

    if (tid < 128) {
        int cp = ct * 128 + tid;
        float sc = 0.f;
        int px = 0;
        if (cp < cnt) {
            px = g_plist[cp];
            int h = px / WW, w = px % WW;
            const float* alive = state + ((size_t)b * CC + 3) * PX;
            float mx = -1e30f;
#pragma unroll
            for (int dy = -1; dy <= 1; dy++)
#pragma unroll
                for (int dx = -1; dx <= 1; dx++) {
                    int hh = h + dy, ww2 = w + dx;
                    if (hh >= 0 && hh < HH && ww2 >= 0 && ww2 < WW)
                        mx = fmaxf(mx, alive[hh * WW + ww2]);
                }
            sc = (mx > 0.1f) ? 1.f : 0.f;
        }
        scl[tid] = sc;
        spx[tid] = px;
    }

    int m0 = (wid & 3) * 32;
    int n0 = (wid >> 2) * 32;
    int a_row  = m0 + (lane & 15);
    int a_byte = (lane >> 4) << 4;
    int qq     = lane >> 3;
    int b_row  = n0 + ((qq >> 1) << 3) + (lane & 7);
    int b_byte = (qq & 1) << 4;

    const __half* Yb = g_y + (size_t)b * PXP * M1;

    // prologue: stage B chunk 0 + y chunk 0
    {
#pragma unroll
        for (int i = 0; i < 2; i++) {
            int g = tid + i * 256, r = g >> 3, u = g & 7;
            cp16(sBb + SW128(r * 128 + u * 16), g_w2h + (size_t)r * M1 + u * 8);
        }
#pragma unroll
        for (int i = 0; i < 4; i++) {
            int g = tid + i * 256, r = g >> 3, u = g & 7;
            int cp = ct * 128 + r;
            cp16(yb + r * 128 + u * 16, Yb + (size_t)cp * M1 + u * 8);
        }
        CP_COMMIT();
    }
    CP_WAIT(0);
    __syncthreads();

    float acc[2][4][4] = {};

#pragma unroll 1
    for (int ch = 0; ch < 8; ch++) {
        int c0 = ch * 64;
#pragma unroll
        for (int i = 0; i < 4; i++) {
            int g = tid + i * 256, r = g >> 3, u = g & 7;
            int cp = ct * 128 + r;
            uint4 hv = make_uint4(0, 0, 0, 0);
            if (cp < cnt) {
                int px = spx[r];
                uint4 yv = *reinterpret_cast<const uint4*>(ybg + r * 128 + u * 16);
                const __half2* wbp = g_lnwb + (size_t)px * M1 + c0 + u * 8;
                uint4 wb0 = *reinterpret_cast<const uint4*>(wbp);
                uint4 wb1 = *reinterpret_cast<const uint4*>(wbp + 4);
                const __half* yh = reinterpret_cast<const __half*>(&yv);
                const __half2* w0q = reinterpret_cast<const __half2*>(&wb0);
                const __half2* w1q = reinterpret_cast<const __half2*>(&wb1);
                __half z[8];
#pragma unroll
                for (int e = 0; e < 8; e++) {
                    __half2 wb = (e < 4) ? w0q[e] : w1q[e - 4];
                    float y  = __half2float(yh[e]);
                    float wv = __half2float(__low2half(wb));
                    float bv = __half2float(__high2half(wb));
                    z[e] = __float2half_rn(fmaxf((y - mu) * rstd * wv + bv, 0.f));
                }
                hv = make_uint4(pack2h(z[0], z[1]), pack2h(z[2], z[3]),
                                pack2h(z[4], z[5]), pack2h(z[6], z[7]));
            }
            sts128(sA + SW128(r * 128 + u * 16), hv);
        }
        __syncthreads();

        if (ch < 7) {
            int c1 = (ch + 1) * 64;
            uint32_t sBn = sBb + ((ch + 1) & 1) * 8192;
#pragma unroll
            for (int i = 0; i < 2; i++) {
                int g = tid + i * 256, r = g >> 3, u = g & 7;
                cp16(sBn + SW128(r * 128 + u * 16), g_w2h + (size_t)r * M1 + c1 + u * 8);
            }
#pragma unroll
            for (int i = 0; i < 4; i++) {
                int g = tid + i * 256, r = g >> 3, u = g & 7;
                int cp = ct * 128 + r;
                cp16(yb + r * 128 + u * 16, Yb + (size_t)cp * M1 + c1 + u * 8);
            }
            CP_COMMIT();
        }

        uint32_t sB = sBb + (ch & 1) * 8192;
#pragma unroll
        for (int kk = 0; kk < 4; kk++) {
            int kb = kk * 32;
            uint32_t ah[2][4];
#pragma unroll
            for (int mi = 0; mi < 2; mi++)
                ldm_x4(sA + SW128((a_row + mi * 16) * 128 + kb + a_byte),
                       ah[mi][0], ah[mi][1], ah[mi][2], ah[mi][3]);
            uint32_t bh[2][4];
#pragma unroll
            for (int n2 = 0; n2 < 2; n2++)
                ldm_x4(sB + SW128((b_row + n2 * 16) * 128 + kb + b_byte),
                       bh[n2][0], bh[n2][1], bh[n2][2], bh[n2][3]);
#pragma unroll
            for (int mi = 0; mi < 2; mi++)
#pragma unroll
                for (int ni = 0; ni < 4; ni++) {
                    int n2 = ni >> 1, rr = (ni & 1) * 2;
                    mma_f16(acc[mi][ni], ah[mi], bh[n2][rr], bh[n2][rr + 1]);
                }
        }
        if (ch < 7) CP_WAIT(0);
        __syncthreads();
    }

    // epilogue: scatter out[b][c][px] = state + z * scl for compacted px
#pragma unroll
    for (int mi = 0; mi < 2; mi++)
#pragma unroll
        for (int ni = 0; ni < 4; ni++) {
            int rl0 = m0 + mi * 16 + (lane >> 2);
            int cc  = n0 + ni * 8 + (lane & 3) * 2;
#pragma unroll
            for (int hf = 0; hf < 2; hf++) {
                int rl = rl0 + hf * 8;
                int cp = ct * 128 + rl;
                if (cp < cnt) {
                    int px = spx[rl];
                    float sc = scl[rl];
                    size_t o0 = ((size_t)b * CC + cc) * PX + px;
                    out[o0]      = state[o0]      + acc[mi][ni][hf * 2 + 0] * sc;
                    out[o0 + PX] = state[o0 + PX] + acc[mi][ni][hf * 2 + 1] * sc;
                }
            }
        }
}

// ---------------------------------------------------------------------------
extern "C" void kernel_launch(void* const* d_in, const int* in_sizes, int n_in,
                              void* d_out, int out_size) {
    const float* state = (const float*)d_in[0];
    const float* w1    = (const float*)d_in[1];
    const float* lnw   = (const float*)d_in[2];
    const float* lnb   = (const float*)d_in[3];
    const float* w2    = (const float*)d_in[4];
    const int*   mask  = (const int*)d_in[5];
    float* out = (float*)d_out;

    cudaFuncSetAttribute(gemm1_kernel, cudaFuncAttributeMaxDynamicSharedMemorySize, 90112);
    cudaFuncSetAttribute(gemm2_kernel, cudaFuncAttributeMaxDynamicSharedMemorySize, 49152);

    pre_kernel<<<NB_PRE, 320>>>(state, w1, w2, lnw, lnb, mask, out);
    gemm1_kernel<<<dim3(2, 26, BB), 256, 90112>>>();
    stats_kernel<<<1, 128>>>();
    gemm2_kernel<<<dim3(13, BB), 256, 49152>>>(state, out);   // profiler slot 4
}

// round 16
// speedup vs baseline: 1.0353x; 1.0353x over previous
#include <cuda_runtime.h>
#include <cuda_fp16.h>
#include <cstdint>

// ---------------------------------------------------------------------------
// Problem constants
// ---------------------------------------------------------------------------
constexpr int BB   = 128;
constexpr int CC   = 64;
constexpr int K1   = 192;    // 3*C perception channels
constexpr int M1   = 512;    // MLP dim
constexpr int HH   = 40;
constexpr int WW   = 40;
constexpr int PX   = 1600;   // H*W
constexpr int PXP  = 1664;   // padded to 26*64
constexpr float LN_EPS = 1e-5f;

// ---------------------------------------------------------------------------
// Device scratch
// ---------------------------------------------------------------------------
__device__ __half  g_perc[(size_t)BB * PXP * K1];   // 81 MB fp16
__device__ __half  g_y[(size_t)BB * PXP * M1];      // 218 MB fp16 (compacted rows)
__device__ __half  g_w1h[M1 * K1];                  // [512][192] fp16
__device__ __half  g_w2h[CC * M1];                  // [64][512] fp16
__device__ __half2 g_lnwb[(size_t)PX * M1];         // [p][m] packed (w, b) fp16
__device__ float   g_part[BB * 52 * 2];
__device__ float   g_stats[BB * 2];
__device__ int     g_plist[PX];                     // compacted px list
__device__ int     g_cidx[PX];                      // px -> compact idx or -1
__device__ int     g_cnt;

// ---------------------------------------------------------------------------
// Helpers (base-ISA only: ldmatrix / mma.sync / cp.async)
// ---------------------------------------------------------------------------
__device__ __forceinline__ uint32_t smem_u32(const void* p) {
    uint32_t a;
    asm("{ .reg .u64 t; cvta.to.shared.u64 t, %1; cvt.u32.u64 %0, t; }"
        : "=r"(a) : "l"(p));
    return a;
}
#define SW128(o) ((o) ^ (((o) >> 3) & 0x70))

__device__ __forceinline__ void sts128(uint32_t a, uint4 v) {
    asm volatile("st.shared.v4.b32 [%0], {%1,%2,%3,%4};"
                 :: "r"(a), "r"(v.x), "r"(v.y), "r"(v.z), "r"(v.w) : "memory");
}
__device__ __forceinline__ void cp16(uint32_t dst, const void* src) {
    asm volatile("cp.async.cg.shared.global [%0], [%1], 16;"
                 :: "r"(dst), "l"(src) : "memory");
}
#define CP_COMMIT() asm volatile("cp.async.commit_group;" ::: "memory")
#define CP_WAIT(n)  asm volatile("cp.async.wait_group %0;" :: "n"(n) : "memory")

__device__ __forceinline__ void ldm_x4(uint32_t addr, uint32_t& r0, uint32_t& r1,
                                       uint32_t& r2, uint32_t& r3) {
    asm volatile("ldmatrix.sync.aligned.m8n8.x4.shared.b16 {%0,%1,%2,%3}, [%4];"
                 : "=r"(r0), "=r"(r1), "=r"(r2), "=r"(r3) : "r"(addr));
}
__device__ __forceinline__ void mma_f16(float* c, const uint32_t* a,
                                        uint32_t b0, uint32_t b1) {
    asm volatile(
        "mma.sync.aligned.m16n8k16.row.col.f32.f16.f16.f32 "
        "{%0,%1,%2,%3},{%4,%5,%6,%7},{%8,%9},{%0,%1,%2,%3};"
        : "+f"(c[0]), "+f"(c[1]), "+f"(c[2]), "+f"(c[3])
        : "r"(a[0]), "r"(a[1]), "r"(a[2]), "r"(a[3]), "r"(b0), "r"(b1));
}

__device__ __forceinline__ uint32_t pack2h(__half a, __half b) {
    return (uint32_t)__half_as_ushort(a) | ((uint32_t)__half_as_ushort(b) << 16);
}

// ---------------------------------------------------------------------------
// Kernel 1 (fused pre): perc(2 rows/block) | w-casts | perc-pad | compact |
//   lnwb transpose. 320 threads/block, block ranges.
// ---------------------------------------------------------------------------
constexpr int NB_PERC = (HH / 2) * BB;         // 2560
constexpr int WPREP_TOTAL = M1 * K1 + CC * M1; // 131072
constexpr int NB_W    = (WPREP_TOTAL + 319) / 320;   // 410
constexpr int NB_PAD  = BB;                    // 128
constexpr int NB_LNT  = (M1 / 32) * (PX / 32); // 800
constexpr int NB_PRE  = NB_PERC + NB_W + NB_PAD + 1 + NB_LNT;

__global__ __launch_bounds__(320) void pre_kernel(
    const float* __restrict__ state, const float* __restrict__ w1,
    const float* __restrict__ w2, const float* __restrict__ lnw,
    const float* __restrict__ lnb, const int* __restrict__ mask,
    float* __restrict__ out) {
    __shared__ __align__(16) char fsm[30720];
    int bx = blockIdx.x;
    int tid = threadIdx.x;

    if (bx < NB_PERC) {
        // ---- perception: 2 output rows per block (4-row halo load) ----
        __half (*sp)[K1] = reinterpret_cast<__half(*)[K1]>(fsm);   // [80][192]
        int hp = bx % (HH / 2);
        int b  = bx / (HH / 2);
        int h0 = hp * 2;
        int c   = tid / 5;
        int seg = tid % 5;
        int w0  = seg * 8;
        const float* s = state + ((size_t)b * CC + c) * PX;
        float v[4][10];
#pragma unroll
        for (int r = 0; r < 4; r++) {
            int hh = h0 + r - 1;
            if (hh >= 0 && hh < HH) {
                const float* rp = s + hh * WW;
                float4 a = *reinterpret_cast<const float4*>(rp + w0);
                float4 d = *reinterpret_cast<const float4*>(rp + w0 + 4);
                v[r][0] = (w0 > 0) ? rp[w0 - 1] : 0.f;
                v[r][1] = a.x; v[r][2] = a.y; v[r][3] = a.z; v[r][4] = a.w;
                v[r][5] = d.x; v[r][6] = d.y; v[r][7] = d.z; v[r][8] = d.w;
                v[r][9] = (w0 + 8 < WW) ? rp[w0 + 8] : 0.f;
            } else {
#pragma unroll
                for (int q = 0; q < 10; q++) v[r][q] = 0.f;
            }
        }
#pragma unroll
        for (int row = 0; row < 2; row++) {
#pragma unroll
            for (int i = 0; i < 8; i++) {
                float sx = -v[row][i] + v[row][i + 2]
                           - 2.f * v[row + 1][i] + 2.f * v[row + 1][i + 2]
                           - v[row + 2][i] + v[row + 2][i + 2];
                float sy = -v[row][i] - 2.f * v[row][i + 1] - v[row][i + 2]
                           + v[row + 2][i] + 2.f * v[row + 2][i + 1] + v[row + 2][i + 2];
                int w = row * WW + w0 + i;
                sp[0][w * K1 + 3 * c + 0] = __float2half_rn(sx);
                sp[0][w * K1 + 3 * c + 1] = __float2half_rn(sy);
                sp[0][w * K1 + 3 * c + 2] = __float2half_rn(v[row + 1][i + 1]);
            }
            // out = state passthrough for this row (center row = v[row+1])
            float* op = out + ((size_t)b * CC + c) * PX + (h0 + row) * WW + w0;
            *reinterpret_cast<float4*>(op) =
                make_float4(v[row + 1][1], v[row + 1][2], v[row + 1][3], v[row + 1][4]);
            *reinterpret_cast<float4*>(op + 4) =
                make_float4(v[row + 1][5], v[row + 1][6], v[row + 1][7], v[row + 1][8]);
        }
        __syncthreads();
        // coalesced store: 80*192 fp16 = 1920 uint4, 320 threads x 6
        const uint4* src = reinterpret_cast<const uint4*>(&sp[0][0]);
        uint4* dst = reinterpret_cast<uint4*>(g_perc + ((size_t)b * PXP + h0 * WW) * K1);
#pragma unroll
        for (int i = 0; i < 6; i++) dst[tid + i * 320] = src[tid + i * 320];
    } else if (bx < NB_PERC + NB_W) {
        // ---- weight casts ----
        int idx = (bx - NB_PERC) * 320 + tid;
        if (idx < M1 * K1) {
            g_w1h[idx] = __float2half_rn(w1[idx]);
        } else if (idx < WPREP_TOTAL) {
            int j = idx - M1 * K1;
            g_w2h[j] = __float2half_rn(w2[j]);
        }
    } else if (bx < NB_PERC + NB_W + NB_PAD) {
        // ---- perc pad rows (px 1600..1663): 1536 uint4 per b ----
        int b = bx - NB_PERC - NB_W;
        uint4 z = make_uint4(0, 0, 0, 0);
        uint4* dst = reinterpret_cast<uint4*>(g_perc + ((size_t)b * PXP + PX) * K1);
#pragma unroll
        for (int i = 0; i < 5; i++) {
            int j = tid + i * 320;
            if (j < 1536) dst[j] = z;
        }
    } else if (bx == NB_PERC + NB_W + NB_PAD) {
        // ---- mask compaction (deterministic) ----
        int* sm = reinterpret_cast<int*>(fsm);
        for (int i = tid; i < PX; i += 320) sm[i] = mask[i];
        __syncthreads();
        if (tid == 0) {
            int c = 0;
            for (int p = 0; p < PX; p++) {
                if (sm[p] != 0) { g_plist[c] = p; g_cidx[p] = c; c++; }
                else            { g_cidx[p] = -1; }
            }
            g_cnt = c;
        }
    } else {
        // ---- lnw+lnb 32x32 tiled transpose -> packed half2 (w, b) ----
        float (*tw)[33] = reinterpret_cast<float(*)[33]>(fsm);
        float (*tb)[33] = reinterpret_cast<float(*)[33]>(fsm + 4224);
        int t = bx - (NB_PERC + NB_W + NB_PAD + 1);
        int pm = t / 50;           // m tile
        int pp = t % 50;           // p tile
        if (tid < 256) {
            int r8 = tid >> 5, cc = tid & 31;
#pragma unroll
            for (int q = 0; q < 4; q++) {
                int r = q * 8 + r8;
                size_t off = (size_t)(pm * 32 + r) * PX + pp * 32 + cc;
                tw[r][cc] = lnw[off];
                tb[r][cc] = lnb[off];
            }
        }
        __syncthreads();
        if (tid < 256) {
            int r8 = tid >> 5, cc = tid & 31;
#pragma unroll
            for (int q = 0; q < 4; q++) {
                int r = q * 8 + r8;
                size_t e = (size_t)(pp * 32 + r) * M1 + pm * 32 + cc;
                g_lnwb[e] = __floats2half2_rn(tw[cc][r], tb[cc][r]);
            }
        }
    }
}

// ---------------------------------------------------------------------------
// Kernel 2: GEMM1 (mma.sync fp16) CTA tile 64px x 256mlp, warp tile 32x64.
//   K=192 (3x64 chunks, 2-stage). 80KB smem, launch_bounds(256,2).
//   Shuffle stats + smem-staged coalesced masked y stores.  (R14 version)
// ---------------------------------------------------------------------------
constexpr int G1_STAGE = 40960;   // A 8KB + B 32KB
constexpr int YT_PITCH = 264;     // fp16 stage tile pitch (conflict-free)

__global__ __launch_bounds__(256, 2) void gemm1_kernel() {
    extern __shared__ char dsm[];
    __shared__ float wred[16];
    uint32_t base = smem_u32(dsm);
    int tid = threadIdx.x;
    int lane = tid & 31, wid = tid >> 5;
    int nt = blockIdx.x;   // 0..1  (mlp half, 256 each)
    int pt = blockIdx.y;   // 0..25 (px tile of 64)
    int b  = blockIdx.z;

    const __half* Ab = g_perc + ((size_t)b * PXP + pt * 64) * K1;
    const __half* Bb = g_w1h + (size_t)(nt * 256) * K1;

    int m0 = (wid & 1) * 32;
    int n0 = (wid >> 1) * 64;
    int a_row  = m0 + (lane & 15);
    int a_byte = (lane >> 4) << 4;
    int qq     = lane >> 3;
    int b_row  = n0 + ((qq >> 1) << 3) + (lane & 7);
    int b_byte = (qq & 1) << 4;

    float acc[2][8][4] = {};

    // prologue: stage 0 (k-offset 0)
    {
        uint32_t sA = base, sB = base + 8192;
#pragma unroll
        for (int i = 0; i < 2; i++) {
            int g = tid + i * 256, r = g >> 3, c = g & 7;
            cp16(sA + SW128(r * 128 + c * 16), Ab + (size_t)r * K1 + c * 8);
        }
#pragma unroll
        for (int i = 0; i < 8; i++) {
            int g = tid + i * 256, r = g >> 3, c = g & 7;
            cp16(sB + SW128(r * 128 + c * 16), Bb + (size_t)r * K1 + c * 8);
        }
        CP_COMMIT();
    }

#pragma unroll 1
    for (int ch = 0; ch < 3; ch++) {
        if (ch < 2) {
            int st = (ch + 1) & 1;
            int ko = (ch + 1) * 64;
            uint32_t sA = base + st * G1_STAGE, sB = sA + 8192;
#pragma unroll
            for (int i = 0; i < 2; i++) {
                int g = tid + i * 256, r = g >> 3, c = g & 7;
                cp16(sA + SW128(r * 128 + c * 16), Ab + (size_t)r * K1 + ko + c * 8);
            }
#pragma unroll
            for (int i = 0; i < 8; i++) {
                int g = tid + i * 256, r = g >> 3, c = g & 7;
                cp16(sB + SW128(r * 128 + c * 16), Bb + (size_t)r * K1 + ko + c * 8);
            }
            CP_COMMIT();
            CP_WAIT(1);
        } else {
            CP_WAIT(0);
        }
        __syncthreads();
        uint32_t sA = base + (ch & 1) * G1_STAGE;
        uint32_t sB = sA + 8192;
#pragma unroll
        for (int kk = 0; kk < 4; kk++) {
            int kb = kk * 32;
            uint32_t a[2][4];
#pragma unroll
            for (int mi = 0; mi < 2; mi++)
                ldm_x4(sA + SW128((a_row + mi * 16) * 128 + kb + a_byte),
                       a[mi][0], a[mi][1], a[mi][2], a[mi][3]);
            uint32_t bf[4][4];
#pragma unroll
            for (int n2 = 0; n2 < 4; n2++)
                ldm_x4(sB + SW128((b_row + n2 * 16) * 128 + kb + b_byte),
                       bf[n2][0], bf[n2][1], bf[n2][2], bf[n2][3]);
#pragma unroll
            for (int mi = 0; mi < 2; mi++)
#pragma unroll
                for (int ni = 0; ni < 8; ni++)
                    mma_f16(acc[mi][ni], a[mi],
                            bf[ni >> 1][(ni & 1) * 2], bf[ni >> 1][(ni & 1) * 2 + 1]);
        }
        __syncthreads();
    }

    // ---- epilogue ----
    float s = 0.f, s2 = 0.f;
#pragma unroll
    for (int mi = 0; mi < 2; mi++)
#pragma unroll
        for (int ni = 0; ni < 8; ni++) {
            float* c = acc[mi][ni];
            s  += c[0] + c[1] + c[2] + c[3];
            s2 += c[0] * c[0] + c[1] * c[1] + c[2] * c[2] + c[3] * c[3];
        }
#pragma unroll
    for (int o = 16; o > 0; o >>= 1) {
        s  += __shfl_xor_sync(0xffffffffu, s, o);
        s2 += __shfl_xor_sync(0xffffffffu, s2, o);
    }
    if (lane == 0) { wred[wid] = s; wred[8 + wid] = s2; }

    // stage y fp16 into conflict-free tile [64][YT_PITCH]
    __half* yt = reinterpret_cast<__half*>(dsm);
    int cb = n0 + (lane & 3) * 2;
#pragma unroll
    for (int mi = 0; mi < 2; mi++)
#pragma unroll
        for (int half = 0; half < 2; half++) {
            int r = m0 + mi * 16 + (lane >> 2) + half * 8;
            __half* rowp = yt + r * YT_PITCH + cb;
#pragma unroll
            for (int ni = 0; ni < 8; ni++)
                *reinterpret_cast<__half2*>(rowp + ni * 8) =
                    __floats2half2_rn(acc[mi][ni][half * 2], acc[mi][ni][half * 2 + 1]);
        }
    __syncthreads();

    if (tid == 0) {
        float a = 0.f;
#pragma unroll
        for (int i = 0; i < 8; i++) a += wred[i];
        g_part[((b * 26 + pt) * 2 + nt) * 2 + 0] = a;
    } else if (tid == 1) {
        float a = 0.f;
#pragma unroll
        for (int i = 0; i < 8; i++) a += wred[8 + i];
        g_part[((b * 26 + pt) * 2 + nt) * 2 + 1] = a;
    }

    // coalesced masked y copy: one warp per row, 512B uint4 sweep
#pragma unroll
    for (int pass = 0; pass < 8; pass++) {
        int r  = wid + pass * 8;
        int px = pt * 64 + r;
        int ci = (px < PX) ? g_cidx[px] : -1;
        if (ci >= 0) {
            uint4 v = *reinterpret_cast<const uint4*>(yt + r * YT_PITCH + lane * 8);
            *reinterpret_cast<uint4*>(g_y + ((size_t)b * PXP + ci) * M1
                                      + nt * 256 + lane * 8) = v;
        }
    }
}

// ---------------------------------------------------------------------------
// Kernel 3: per-sample LN stats (deterministic fixed order)
// ---------------------------------------------------------------------------
__global__ void stats_kernel() {
    int b = threadIdx.x;
    if (b >= BB) return;
    float s = 0.f, s2 = 0.f;
    for (int i = 0; i < 52; i++) {
        s  += g_part[(b * 52 + i) * 2 + 0];
        s2 += g_part[(b * 52 + i) * 2 + 1];
    }
    float inv = 1.f / (float)(M1 * PX);
    float mu  = s * inv;
    float var = s2 * inv - mu * mu;
    g_stats[b * 2 + 0] = mu;
    g_stats[b * 2 + 1] = rsqrtf(var + LN_EPS);
}

// ---------------------------------------------------------------------------
// Kernel 4: GEMM2 over COMPACTED pixels — PIPELINED (R14 version, no cap).
//   smem: sA 16KB | sB 2x8KB | ybuf 16KB = 48KB.
// ---------------------------------------------------------------------------
__global__ __launch_bounds__(256) void gemm2_kernel(
    const float* __restrict__ state, float* __restrict__ out) {
    extern __shared__ char dsm[];
    __shared__ float scl[128];
    __shared__ int   spx[128];
    uint32_t sA  = smem_u32(dsm);
    uint32_t sBb = sA + 16384;
    uint32_t yb  = sA + 32768;
    char* ybg = dsm + 32768;

    int cnt = g_cnt;
    int ct = blockIdx.x;
    if (ct * 128 >= cnt) return;
    int b  = blockIdx.y;

    int tid = threadIdx.x, lane = tid & 31, wid = tid >> 5;
    float mu   = g_stats[b * 2 + 0];
    float rstd = g_stats[b * 2 + 1];

    if (tid < 128) {
        int cp = ct * 128 + tid;
        float sc = 0.f;
        int px = 0;
        if (cp < cnt) {
            px = g_plist[cp];
            int h = px / WW, w = px % WW;
            const float* alive = state + ((size_t)b * CC + 3) * PX;
            float mx = -1e30f;
#pragma unroll
            for (int dy = -1; dy <= 1; dy++)
#pragma unroll
                for (int dx = -1; dx <= 1; dx++) {
                    int hh = h + dy, ww2 = w + dx;
                    if (hh >= 0 && hh < HH && ww2 >= 0 && ww2 < WW)
                        mx = fmaxf(mx, alive[hh * WW + ww2]);
                }
            sc = (mx > 0.1f) ? 1.f : 0.f;
        }
        scl[tid] = sc;
        spx[tid] = px;
    }

    int m0 = (wid & 3) * 32;
    int n0 = (wid >> 2) * 32;
    int a_row  = m0 + (lane & 15);
    int a_byte = (lane >> 4) << 4;
    int qq     = lane >> 3;
    int b_row  = n0 + ((qq >> 1) << 3) + (lane & 7);
    int b_byte = (qq & 1) << 4;

    const __half* Yb = g_y + (size_t)b * PXP * M1;

    // prologue: stage B chunk 0 + y chunk 0
    {
#pragma unroll
        for (int i = 0; i < 2; i++) {
            int g = tid + i * 256, r = g >> 3, u = g & 7;
            cp16(sBb + SW128(r * 128 + u * 16), g_w2h + (size_t)r * M1 + u * 8);
        }
#pragma unroll
        for (int i = 0; i < 4; i++) {
            int g = tid + i * 256, r = g >> 3, u = g & 7;
            int cp = ct * 128 + r;
            cp16(yb + r * 128 + u * 16, Yb + (size_t)cp * M1 + u * 8);
        }
        CP_COMMIT();
    }
    CP_WAIT(0);
    __syncthreads();

    float acc[2][4][4] = {};

#pragma unroll 1
    for (int ch = 0; ch < 8; ch++) {
        int c0 = ch * 64;
#pragma unroll
        for (int i = 0; i < 4; i++) {
            int g = tid + i * 256, r = g >> 3, u = g & 7;
            int cp = ct * 128 + r;
            uint4 hv = make_uint4(0, 0, 0, 0);
            if (cp < cnt) {
                int px = spx[r];
                uint4 yv = *reinterpret_cast<const uint4*>(ybg + r * 128 + u * 16);
                const __half2* wbp = g_lnwb + (size_t)px * M1 + c0 + u * 8;
                uint4 wb0 = *reinterpret_cast<const uint4*>(wbp);
                uint4 wb1 = *reinterpret_cast<const uint4*>(wbp + 4);
                const __half* yh = reinterpret_cast<const __half*>(&yv);
                const __half2* w0q = reinterpret_cast<const __half2*>(&wb0);
                const __half2* w1q = reinterpret_cast<const __half2*>(&wb1);
                __half z[8];
#pragma unroll
                for (int e = 0; e < 8; e++) {
                    __half2 wb = (e < 4) ? w0q[e] : w1q[e - 4];
                    float y  = __half2float(yh[e]);
                    float wv = __half2float(__low2half(wb));
                    float bv = __half2float(__high2half(wb));
                    z[e] = __float2half_rn(fmaxf((y - mu) * rstd * wv + bv, 0.f));
                }
                hv = make_uint4(pack2h(z[0], z[1]), pack2h(z[2], z[3]),
                                pack2h(z[4], z[5]), pack2h(z[6], z[7]));
            }
            sts128(sA + SW128(r * 128 + u * 16), hv);
        }
        __syncthreads();

        if (ch < 7) {
            int c1 = (ch + 1) * 64;
            uint32_t sBn = sBb + ((ch + 1) & 1) * 8192;
#pragma unroll
            for (int i = 0; i < 2; i++) {
                int g = tid + i * 256, r = g >> 3, u = g & 7;
                cp16(sBn + SW128(r * 128 + u * 16), g_w2h + (size_t)r * M1 + c1 + u * 8);
            }
#pragma unroll
            for (int i = 0; i < 4; i++) {
                int g = tid + i * 256, r = g >> 3, u = g & 7;
                int cp = ct * 128 + r;
                cp16(yb + r * 128 + u * 16, Yb + (size_t)cp * M1 + c1 + u * 8);
            }
            CP_COMMIT();
        }

        uint32_t sB = sBb + (ch & 1) * 8192;
#pragma unroll
        for (int kk = 0; kk < 4; kk++) {
            int kb = kk * 32;
            uint32_t ah[2][4];
#pragma unroll
            for (int mi = 0; mi < 2; mi++)
                ldm_x4(sA + SW128((a_row + mi * 16) * 128 + kb + a_byte),
                       ah[mi][0], ah[mi][1], ah[mi][2], ah[mi][3]);
            uint32_t bh[2][4];
#pragma unroll
            for (int n2 = 0; n2 < 2; n2++)
                ldm_x4(sB + SW128((b_row + n2 * 16) * 128 + kb + b_byte),
                       bh[n2][0], bh[n2][1], bh[n2][2], bh[n2][3]);
#pragma unroll
            for (int mi = 0; mi < 2; mi++)
#pragma unroll
                for (int ni = 0; ni < 4; ni++) {
                    int n2 = ni >> 1, rr = (ni & 1) * 2;
                    mma_f16(acc[mi][ni], ah[mi], bh[n2][rr], bh[n2][rr + 1]);
                }
        }
        if (ch < 7) CP_WAIT(0);
        __syncthreads();
    }

    // epilogue: scatter out[b][c][px] = state + z * scl for compacted px
#pragma unroll
    for (int mi = 0; mi < 2; mi++)
#pragma unroll
        for (int ni = 0; ni < 4; ni++) {
            int rl0 = m0 + mi * 16 + (lane >> 2);
            int cc  = n0 + ni * 8 + (lane & 3) * 2;
#pragma unroll
            for (int hf = 0; hf < 2; hf++) {
                int rl = rl0 + hf * 8;
                int cp = ct * 128 + rl;
                if (cp < cnt) {
                    int px = spx[rl];
                    float sc = scl[rl];
                    size_t o0 = ((size_t)b * CC + cc) * PX + px;
                    out[o0]      = state[o0]      + acc[mi][ni][hf * 2 + 0] * sc;
                    out[o0 + PX] = state[o0 + PX] + acc[mi][ni][hf * 2 + 1] * sc;
                }
            }
        }
}

// ---------------------------------------------------------------------------
extern "C" void kernel_launch(void* const* d_in, const int* in_sizes, int n_in,
                              void* d_out, int out_size) {
    const float* state = (const float*)d_in[0];
    const float* w1    = (const float*)d_in[1];
    const float* lnw   = (const float*)d_in[2];
    const float* lnb   = (const float*)d_in[3];
    const float* w2    = (const float*)d_in[4];
    const int*   mask  = (const int*)d_in[5];
    float* out = (float*)d_out;

    cudaFuncSetAttribute(gemm1_kernel, cudaFuncAttributeMaxDynamicSharedMemorySize, 81920);
    cudaFuncSetAttribute(gemm2_kernel, cudaFuncAttributeMaxDynamicSharedMemorySize, 49152);

    pre_kernel<<<NB_PRE, 320>>>(state, w1, w2, lnw, lnb, mask, out);
    gemm1_kernel<<<dim3(2, 26, BB), 256, 81920>>>();
    stats_kernel<<<1, 128>>>();
    gemm2_kernel<<<dim3(13, BB), 256, 49152>>>(state, out);   // profiler slot 4
}